// round 16
// baseline (speedup 1.0000x reference)
#include <cuda_runtime.h>
#include <cuda_fp16.h>
#include <cstdint>

// ---------------- problem constants ----------------
#define M_ROWS 50000
#define M_PAD  50048      // 391 * 128
#define Q_COLS 3136
#define Q_PAD  3328       // 13 * 256
#define DDIM   1024
#define BATCH  4
#define GH     28
#define OH     224

#define MT 128
#define NT 256
#define KC 64             // fp16 elements per K chunk
#define KCHUNKS 16        // 1024 / 64
#define NSTAGE 2

// smem tile: row = 64 halves (128 B) + 16 B pad -> stride 144 B, conflict-free ldmatrix
#define RSTRIDE_B 144
#define ATILE_B   (128 * RSTRIDE_B)     // 18432
#define BTILE_B   (256 * RSTRIDE_B)     // 36864
#define STAGE_B   (ATILE_B + BTILE_B)   // 55296 (A then B)
#define SMEM_BYTES (NSTAGE * STAGE_B)   // 110592

// ---------------- device globals (scratch; no cudaMalloc allowed) ----------------
__device__ __align__(16) __half g_A[(size_t)M_PAD * DDIM];   // ~102.5 MB
__device__ __align__(16) __half g_B[(size_t)Q_PAD * DDIM];   // ~6.8 MB
__device__ float    g_a2[M_PAD];
__device__ float    g_b2[Q_PAD];
__device__ unsigned g_minkey[Q_PAD];
__device__ float    g_patch[Q_COLS];
__device__ float    g_tmp[BATCH*OH*OH];

// ---------------- helpers ----------------
__device__ __forceinline__ uint32_t smem_u32(const void* p) {
    uint32_t a;
    asm("{ .reg .u64 t; cvta.to.shared.u64 t, %1; cvt.u32.u64 %0, t; }" : "=r"(a) : "l"(p));
    return a;
}
__device__ __forceinline__ void cpasync16(uint32_t smaddr, const void* g) {
    asm volatile("cp.async.cg.shared.global [%0], [%1], 16;" :: "r"(smaddr), "l"(g) : "memory");
}
__device__ __forceinline__ void ldmatrix_x4(uint32_t r[4], uint32_t addr) {
    asm volatile("ldmatrix.sync.aligned.m8n8.x4.shared.b16 {%0,%1,%2,%3}, [%4];"
        : "=r"(r[0]), "=r"(r[1]), "=r"(r[2]), "=r"(r[3]) : "r"(addr));
}
// fp16 x fp16 -> fp16 accumulate (full-rate legacy path)
__device__ __forceinline__ void mma16816_f16(uint32_t c[2], const uint32_t a[4], uint32_t b0, uint32_t b1) {
    asm volatile("mma.sync.aligned.m16n8k16.row.col.f16.f16.f16.f16 "
        "{%0,%1}, {%2,%3,%4,%5}, {%6,%7}, {%0,%1};"
        : "+r"(c[0]), "+r"(c[1])
        : "r"(a[0]), "r"(a[1]), "r"(a[2]), "r"(a[3]), "r"(b0), "r"(b1));
}
__device__ __forceinline__ unsigned fkey(float f) {
    unsigned u = __float_as_uint(f);
    return (u & 0x80000000u) ? ~u : (u | 0x80000000u);
}

// ---------------- convert fp32 -> fp16 + row sum of squares (A and B fused) ----------------
__device__ __forceinline__ void convert_rows(const float* __restrict__ src, __half* __restrict__ dst,
                                             float* __restrict__ sq, int blk, int nrows, int nrows_pad,
                                             float padval) {
    int row = blk * 8 + (threadIdx.x >> 5);
    int lane = threadIdx.x & 31;
    if (row >= nrows_pad) return;
    if (row >= nrows) {
        uint4 z = make_uint4(0, 0, 0, 0);
        uint4* drow = (uint4*)(dst + (size_t)row * DDIM);
        for (int j = lane; j < 128; j += 32) drow[j] = z;
        if (lane == 0) sq[row] = padval;
        return;
    }
    const float4* srow = (const float4*)(src + (size_t)row * DDIM);
    uint2* drow = (uint2*)(dst + (size_t)row * DDIM);
    float acc = 0.f;
#pragma unroll
    for (int j = 0; j < 8; j++) {
        float4 x = srow[j * 32 + lane];
        acc = fmaf(x.x, x.x, fmaf(x.y, x.y, fmaf(x.z, x.z, fmaf(x.w, x.w, acc))));
        __half2 p0 = __floats2half2_rn(x.x, x.y);
        __half2 p1 = __floats2half2_rn(x.z, x.w);
        uint2 o; o.x = *(uint32_t*)&p0; o.y = *(uint32_t*)&p1;
        drow[j * 32 + lane] = o;
    }
#pragma unroll
    for (int o = 16; o > 0; o >>= 1) acc += __shfl_xor_sync(0xFFFFFFFFu, acc, o);
    if (lane == 0) sq[row] = acc;
}

#define A_BLOCKS (M_PAD / 8)   // 6256
#define B_BLOCKS (Q_PAD / 8)   // 416

__global__ void convert_all_kernel(const float* __restrict__ coreset, const float* __restrict__ features) {
    if (blockIdx.x < A_BLOCKS) {
        convert_rows(coreset, g_A, g_a2, blockIdx.x, M_ROWS, M_PAD, 3.402823466e38f);
    } else {
        int bb = blockIdx.x - A_BLOCKS;
        int i = bb * 256 + threadIdx.x;
        if (i < Q_PAD) g_minkey[i] = 0xFFFFFFFFu;
        convert_rows(features, g_B, g_b2, bb, Q_COLS, Q_PAD, 0.f);
    }
}

// ---------------- main GEMM-with-min kernel (f16-acc, 64x64 warp tile, B-frag double-buffer) ----------------
__global__ void __launch_bounds__(256, 2) gemm_min_kernel() {
    extern __shared__ __align__(16) char smem[];          // NSTAGE * STAGE_B
    __shared__ unsigned colmin[NT];

    const int tid = threadIdx.x;
    const int lane = tid & 31, wid = tid >> 5;
    const int warp_m = wid & 1;          // 0..1 -> 64-row slice of A
    const int warp_n = wid >> 1;         // 0..3 -> 64-col slice of B
    const size_t m0 = (size_t)blockIdx.y * MT;
    const size_t n0 = (size_t)blockIdx.x * NT;

    // warps whose entire 64-col slice is padding do no tensor work (last x-tile)
    const bool active = (n0 + (size_t)warp_n * 64) < (size_t)Q_COLS;

    if (tid < NT) colmin[tid] = 0xFFFFFFFFu;

    const uint32_t sb = smem_u32(smem);
    const char* gA = (const char*)(g_A + m0 * DDIM);
    const char* gB = (const char*)(g_B + n0 * DDIM);

    // copy: A 128 rows + B 256 rows, 8 vec16 per row; thread -> row rr+32t, col byte cb
    const int rr = tid >> 3;
    const int cb = (tid & 7) * 16;

#define STAGE_COPY(stg, kc)                                                                  \
    do {                                                                                     \
        uint32_t s = sb + (uint32_t)(stg) * STAGE_B;                                         \
        const char* ga = gA + (size_t)(kc) * (KC * 2) + cb;                                  \
        const char* gb = gB + (size_t)(kc) * (KC * 2) + cb;                                  \
        _Pragma("unroll")                                                                    \
        for (int t = 0; t < 4; t++) {                                                        \
            int row = rr + 32 * t;                                                           \
            cpasync16(s + row * RSTRIDE_B + cb, ga + (size_t)row * 2048);                    \
        }                                                                                    \
        _Pragma("unroll")                                                                    \
        for (int t = 0; t < 8; t++) {                                                        \
            int row = rr + 32 * t;                                                           \
            cpasync16(s + ATILE_B + row * RSTRIDE_B + cb, gb + (size_t)row * 2048);          \
        }                                                                                    \
        asm volatile("cp.async.commit_group;" ::: "memory");                                 \
    } while (0)

    // ldmatrix per-lane base offset: matrix j = lane>>3
    const int j = lane >> 3, l7 = lane & 7;
    const uint32_t laneoff = (uint32_t)(((j & 1) * 8 + l7) * RSTRIDE_B + (j >> 1) * 16);

    uint32_t hacc[4][8][2];
#pragma unroll
    for (int mi = 0; mi < 4; mi++)
#pragma unroll
        for (int nj = 0; nj < 8; nj++) { hacc[mi][nj][0] = 0u; hacc[mi][nj][1] = 0u; }

    // prologue: stage 0
    STAGE_COPY(0, 0);
    asm volatile("cp.async.wait_group 0;" ::: "memory");
    __syncthreads();

#pragma unroll 1
    for (int kc = 0; kc < KCHUNKS; kc++) {
        // issue next stage copy first -> lands during this chunk's compute
        if (kc + 1 < KCHUNKS) STAGE_COPY((kc + 1) & 1, kc + 1);

        const uint32_t stg = sb + (uint32_t)(kc & 1) * STAGE_B;
        const uint32_t sA = stg + (uint32_t)(warp_m * 64 * RSTRIDE_B) + laneoff;
        const uint32_t sB = stg + ATILE_B + (uint32_t)(warp_n * 64 * RSTRIDE_B) + laneoff;

        if (active) {
            uint32_t bf[2][4][4];           // double-buffered B fragments (+16 regs)
            // preload quarter 0 B frags
#pragma unroll
            for (int np = 0; np < 4; np++) ldmatrix_x4(bf[0][np], sB + np * (16 * RSTRIDE_B));

#pragma unroll
            for (int kh = 0; kh < 4; kh++) {
                const int cur = kh & 1, nxt = cur ^ 1;
                const uint32_t ka = kh * 32;                   // 16 halves = 32 bytes
                uint32_t af[4][4];
#pragma unroll
                for (int mi = 0; mi < 4; mi++) ldmatrix_x4(af[mi], sA + mi * (16 * RSTRIDE_B) + ka);
                if (kh < 3) {
                    const uint32_t kn = (kh + 1) * 32;         // prefetch next-quarter B frags
#pragma unroll
                    for (int np = 0; np < 4; np++) ldmatrix_x4(bf[nxt][np], sB + np * (16 * RSTRIDE_B) + kn);
                }
#pragma unroll
                for (int mi = 0; mi < 4; mi++) {
#pragma unroll
                    for (int nj = 0; nj < 8; nj++) {
                        const int np = nj >> 1, h = nj & 1;
                        mma16816_f16(hacc[mi][nj], af[mi], bf[cur][np][h], bf[cur][np][h + 2]);
                    }
                }
            }
        }

        if (kc + 1 < KCHUNKS) {
            asm volatile("cp.async.wait_group 0;" ::: "memory");
            __syncthreads();   // next stage visible; this stage free for overwrite next iter
        }
    }

    // ---------------- epilogue: s = a2[m] - 2*ab, min over m ----------------
    if (active) {
        float a2r[8];
        {
            const float* a2p = g_a2 + m0 + warp_m * 64 + (lane >> 2);
#pragma unroll
            for (int mi = 0; mi < 4; mi++) {
                a2r[2 * mi]     = a2p[mi * 16];
                a2r[2 * mi + 1] = a2p[mi * 16 + 8];
            }
        }
        float v[16];
#pragma unroll
        for (int i = 0; i < 16; i++) v[i] = 3.402823466e38f;
#pragma unroll
        for (int mi = 0; mi < 4; mi++) {
#pragma unroll
            for (int nj = 0; nj < 8; nj++) {
                float2 h0 = __half22float2(*(const __half2*)&hacc[mi][nj][0]);  // row r,   cols n,n+1
                float2 h1 = __half22float2(*(const __half2*)&hacc[mi][nj][1]);  // row r+8, cols n,n+1
                v[nj * 2]     = fminf(v[nj * 2],     fmaf(-2.f, h0.x, a2r[2 * mi]));
                v[nj * 2 + 1] = fminf(v[nj * 2 + 1], fmaf(-2.f, h0.y, a2r[2 * mi]));
                v[nj * 2]     = fminf(v[nj * 2],     fmaf(-2.f, h1.x, a2r[2 * mi + 1]));
                v[nj * 2 + 1] = fminf(v[nj * 2 + 1], fmaf(-2.f, h1.y, a2r[2 * mi + 1]));
            }
        }
#pragma unroll
        for (int o = 4; o <= 16; o <<= 1) {
#pragma unroll
            for (int i = 0; i < 16; i++) v[i] = fminf(v[i], __shfl_xor_sync(0xFFFFFFFFu, v[i], o));
        }
        if (lane < 4) {
#pragma unroll
            for (int nj = 0; nj < 8; nj++) {
                int col = warp_n * 64 + nj * 8 + lane * 2;
                atomicMin(&colmin[col],     fkey(v[nj * 2]));
                atomicMin(&colmin[col + 1], fkey(v[nj * 2 + 1]));
            }
        }
    }
    __syncthreads();
    if (tid < NT) atomicMin(&g_minkey[n0 + tid], colmin[tid]);
#undef STAGE_COPY
}

// ---------------- postprocess: finalize + per-image max (one block per image) ----------------
__global__ void finalize_max_kernel(float* __restrict__ out) {
    int b = blockIdx.x, tid = threadIdx.x;
    float mx = -3.402823466e38f;
    for (int i = tid; i < GH * GH; i += 256) {
        int q = b * GH * GH + i;
        unsigned k = g_minkey[q];
        unsigned bits = (k & 0x80000000u) ? (k ^ 0x80000000u) : ~k;
        float s = __uint_as_float(bits);
        float d = sqrtf(fmaxf(s + g_b2[q], 0.f));
        g_patch[q] = d;
        mx = fmaxf(mx, d);
    }
#pragma unroll
    for (int o = 16; o > 0; o >>= 1) mx = fmaxf(mx, __shfl_xor_sync(0xFFFFFFFFu, mx, o));
    __shared__ float s[8];
    if ((tid & 31) == 0) s[tid >> 5] = mx;
    __syncthreads();
    if (tid == 0) {
        float m = s[0];
#pragma unroll
        for (int i = 1; i < 8; i++) m = fmaxf(m, s[i]);
        out[b] = m;
    }
}

// ---------------- resize (bilinear) + horizontal blur, one block per output row ----------------
__global__ void resize_blur_x_kernel() {
    __shared__ float row[OH];
    __shared__ float w[33];
    int r = blockIdx.x;            // b*224 + y
    int b = r / OH, y = r % OH;
    int x = threadIdx.x;           // 0..223
    if (x < 33) { float t = (float)(x - 16); w[x] = expf(-t * t * (1.0f / 32.0f)); }

    // bilinear sample for (y, x) of image b directly from 28x28 patch grid
    float sy = fminf(fmaxf((y + 0.5f) * 0.125f - 0.5f, 0.f), (float)(GH - 1));
    int y0 = (int)sy; float fy = sy - y0; int y1 = min(y0 + 1, GH - 1);
    float sx = fminf(fmaxf((x + 0.5f) * 0.125f - 0.5f, 0.f), (float)(GH - 1));
    int x0 = (int)sx; float fx = sx - x0; int x1 = min(x0 + 1, GH - 1);
    const float* g = g_patch + b * GH * GH;
    row[x] = (1.f - fy) * ((1.f - fx) * g[y0 * GH + x0] + fx * g[y0 * GH + x1])
           +        fy  * ((1.f - fx) * g[y1 * GH + x0] + fx * g[y1 * GH + x1]);
    __syncthreads();

    float wsum = 0.f;
#pragma unroll
    for (int jj = 0; jj < 33; jj++) wsum += w[jj];
    float acc = 0.f;
#pragma unroll
    for (int t = -16; t <= 16; t++) {
        int ix = x + t;
        ix = (ix < 0) ? -ix : ((ix > OH - 1) ? (2 * OH - 2 - ix) : ix);
        acc += w[t + 16] * row[ix];
    }
    g_tmp[r * OH + x] = acc / wsum;
}

__global__ void blur_y_kernel(float* __restrict__ out) {
    __shared__ float w[33];
    int r = blockIdx.x;            // b*224 + y
    int b = r / OH, y = r % OH;
    int x = threadIdx.x;
    if (x < 33) { float t = (float)(x - 16); w[x] = expf(-t * t * (1.0f / 32.0f)); }
    __syncthreads();
    float wsum = 0.f;
#pragma unroll
    for (int jj = 0; jj < 33; jj++) wsum += w[jj];
    float acc = 0.f;
#pragma unroll
    for (int t = -16; t <= 16; t++) {
        int iy = y + t;
        iy = (iy < 0) ? -iy : ((iy > OH - 1) ? (2 * OH - 2 - iy) : iy);
        acc += w[t + 16] * g_tmp[(b * OH + iy) * OH + x];
    }
    out[r * OH + x] = acc / wsum;
}

// ---------------- launch ----------------
extern "C" void kernel_launch(void* const* d_in, const int* in_sizes, int n_in,
                              void* d_out, int out_size) {
    const float* coreset  = (const float*)d_in[0];
    const float* features = (const float*)d_in[1];
    float* out = (float*)d_out;

    cudaFuncSetAttribute(gemm_min_kernel, cudaFuncAttributeMaxDynamicSharedMemorySize, SMEM_BYTES);

    convert_all_kernel<<<A_BLOCKS + B_BLOCKS, 256>>>(coreset, features);  // A + B + minkey init

    dim3 grid(Q_PAD / NT, M_PAD / MT);   // (13, 391): x inner -> A-tile L2 reuse
    gemm_min_kernel<<<grid, 256, SMEM_BYTES>>>();

    finalize_max_kernel<<<BATCH, 256>>>(out);                    // out[0..3] = image scores
    resize_blur_x_kernel<<<BATCH * OH, OH>>>();
    blur_y_kernel<<<BATCH * OH, OH>>>(out + BATCH);              // out[4..] = masks
}

// round 17
// speedup vs baseline: 1.0089x; 1.0089x over previous
#include <cuda_runtime.h>
#include <cuda_fp16.h>
#include <cstdint>

// ---------------- problem constants ----------------
#define M_ROWS 50000
#define M_PAD  50048      // 391 * 128
#define Q_COLS 3136
#define Q_PAD  3328       // 13 * 256
#define DDIM   1024
#define BATCH  4
#define GH     28
#define OH     224

#define MT 128
#define NT 256
#define KC 64             // fp16 elements per K chunk
#define KCHUNKS 16        // 1024 / 64
#define NSTAGE 2

// smem tile: row = 64 halves (128 B) + 16 B pad -> stride 144 B, conflict-free ldmatrix
#define RSTRIDE_B 144
#define ATILE_B   (128 * RSTRIDE_B)     // 18432
#define BTILE_B   (256 * RSTRIDE_B)     // 36864
#define STAGE_B   (ATILE_B + BTILE_B)   // 55296 (A then B)
#define SMEM_BYTES (NSTAGE * STAGE_B)   // 110592

// ---------------- device globals (scratch; no cudaMalloc allowed) ----------------
__device__ __align__(16) __half g_A[(size_t)M_PAD * DDIM];   // ~102.5 MB
__device__ __align__(16) __half g_B[(size_t)Q_PAD * DDIM];   // ~6.8 MB
__device__ float    g_a2[M_PAD];
__device__ float    g_b2[Q_PAD];
__device__ unsigned g_minkey[Q_PAD];
__device__ float    g_patch[Q_COLS];
__device__ float    g_tmp[BATCH*OH*OH];

// ---------------- helpers ----------------
__device__ __forceinline__ uint32_t smem_u32(const void* p) {
    uint32_t a;
    asm("{ .reg .u64 t; cvta.to.shared.u64 t, %1; cvt.u32.u64 %0, t; }" : "=r"(a) : "l"(p));
    return a;
}
__device__ __forceinline__ void cpasync16(uint32_t smaddr, const void* g) {
    asm volatile("cp.async.cg.shared.global [%0], [%1], 16;" :: "r"(smaddr), "l"(g) : "memory");
}
__device__ __forceinline__ void ldmatrix_x4(uint32_t r[4], uint32_t addr) {
    asm volatile("ldmatrix.sync.aligned.m8n8.x4.shared.b16 {%0,%1,%2,%3}, [%4];"
        : "=r"(r[0]), "=r"(r[1]), "=r"(r[2]), "=r"(r[3]) : "r"(addr));
}
// fp16 x fp16 -> fp16 accumulate (full-rate legacy path)
__device__ __forceinline__ void mma16816_f16(uint32_t c[2], const uint32_t a[4], uint32_t b0, uint32_t b1) {
    asm volatile("mma.sync.aligned.m16n8k16.row.col.f16.f16.f16.f16 "
        "{%0,%1}, {%2,%3,%4,%5}, {%6,%7}, {%0,%1};"
        : "+r"(c[0]), "+r"(c[1])
        : "r"(a[0]), "r"(a[1]), "r"(a[2]), "r"(a[3]), "r"(b0), "r"(b1));
}
__device__ __forceinline__ unsigned fkey(float f) {
    unsigned u = __float_as_uint(f);
    return (u & 0x80000000u) ? ~u : (u | 0x80000000u);
}

// ---------------- convert fp32 -> fp16 + row sum of squares (A and B fused) ----------------
__device__ __forceinline__ void convert_rows(const float* __restrict__ src, __half* __restrict__ dst,
                                             float* __restrict__ sq, int blk, int nrows, int nrows_pad,
                                             float padval) {
    int row = blk * 8 + (threadIdx.x >> 5);
    int lane = threadIdx.x & 31;
    if (row >= nrows_pad) return;
    if (row >= nrows) {
        uint4 z = make_uint4(0, 0, 0, 0);
        uint4* drow = (uint4*)(dst + (size_t)row * DDIM);
        for (int j = lane; j < 128; j += 32) drow[j] = z;
        if (lane == 0) sq[row] = padval;
        return;
    }
    const float4* srow = (const float4*)(src + (size_t)row * DDIM);
    uint2* drow = (uint2*)(dst + (size_t)row * DDIM);
    float acc = 0.f;
#pragma unroll
    for (int j = 0; j < 8; j++) {
        float4 x = srow[j * 32 + lane];
        acc = fmaf(x.x, x.x, fmaf(x.y, x.y, fmaf(x.z, x.z, fmaf(x.w, x.w, acc))));
        __half2 p0 = __floats2half2_rn(x.x, x.y);
        __half2 p1 = __floats2half2_rn(x.z, x.w);
        uint2 o; o.x = *(uint32_t*)&p0; o.y = *(uint32_t*)&p1;
        drow[j * 32 + lane] = o;
    }
#pragma unroll
    for (int o = 16; o > 0; o >>= 1) acc += __shfl_xor_sync(0xFFFFFFFFu, acc, o);
    if (lane == 0) sq[row] = acc;
}

#define A_BLOCKS (M_PAD / 8)   // 6256
#define B_BLOCKS (Q_PAD / 8)   // 416

__global__ void convert_all_kernel(const float* __restrict__ coreset, const float* __restrict__ features) {
    if (blockIdx.x < A_BLOCKS) {
        convert_rows(coreset, g_A, g_a2, blockIdx.x, M_ROWS, M_PAD, 3.402823466e38f);
    } else {
        int bb = blockIdx.x - A_BLOCKS;
        int i = bb * 256 + threadIdx.x;
        if (i < Q_PAD) g_minkey[i] = 0xFFFFFFFFu;
        convert_rows(features, g_B, g_b2, bb, Q_COLS, Q_PAD, 0.f);
    }
}

// ---------------- main GEMM-with-min kernel (f16-acc, 64x64 warp tile, pad predication) ----------------
__global__ void __launch_bounds__(256, 2) gemm_min_kernel() {
    extern __shared__ __align__(16) char smem[];          // NSTAGE * STAGE_B
    __shared__ unsigned colmin[NT];

    const int tid = threadIdx.x;
    const int lane = tid & 31, wid = tid >> 5;
    const int warp_m = wid & 1;          // 0..1 -> 64-row slice of A
    const int warp_n = wid >> 1;         // 0..3 -> 64-col slice of B
    const size_t m0 = (size_t)blockIdx.y * MT;
    const size_t n0 = (size_t)blockIdx.x * NT;

    // warps whose entire 64-col slice is padding do no tensor work (last x-tile)
    const bool active = (n0 + (size_t)warp_n * 64) < (size_t)Q_COLS;

    if (tid < NT) colmin[tid] = 0xFFFFFFFFu;

    const uint32_t sb = smem_u32(smem);
    const char* gA = (const char*)(g_A + m0 * DDIM);
    const char* gB = (const char*)(g_B + n0 * DDIM);

    // copy: A 128 rows + B 256 rows, 8 vec16 per row; thread -> row rr+32t, col byte cb
    const int rr = tid >> 3;
    const int cb = (tid & 7) * 16;

#define STAGE_COPY(stg, kc)                                                                  \
    do {                                                                                     \
        uint32_t s = sb + (uint32_t)(stg) * STAGE_B;                                         \
        const char* ga = gA + (size_t)(kc) * (KC * 2) + cb;                                  \
        const char* gb = gB + (size_t)(kc) * (KC * 2) + cb;                                  \
        _Pragma("unroll")                                                                    \
        for (int t = 0; t < 4; t++) {                                                        \
            int row = rr + 32 * t;                                                           \
            cpasync16(s + row * RSTRIDE_B + cb, ga + (size_t)row * 2048);                    \
        }                                                                                    \
        _Pragma("unroll")                                                                    \
        for (int t = 0; t < 8; t++) {                                                        \
            int row = rr + 32 * t;                                                           \
            cpasync16(s + ATILE_B + row * RSTRIDE_B + cb, gb + (size_t)row * 2048);          \
        }                                                                                    \
        asm volatile("cp.async.commit_group;" ::: "memory");                                 \
    } while (0)

    // ldmatrix per-lane base offset: matrix j = lane>>3
    const int j = lane >> 3, l7 = lane & 7;
    const uint32_t laneoff = (uint32_t)(((j & 1) * 8 + l7) * RSTRIDE_B + (j >> 1) * 16);

    uint32_t hacc[4][8][2];
#pragma unroll
    for (int mi = 0; mi < 4; mi++)
#pragma unroll
        for (int nj = 0; nj < 8; nj++) { hacc[mi][nj][0] = 0u; hacc[mi][nj][1] = 0u; }

    // prologue: stage 0
    STAGE_COPY(0, 0);
    asm volatile("cp.async.wait_group 0;" ::: "memory");
    __syncthreads();

#pragma unroll 1
    for (int kc = 0; kc < KCHUNKS; kc++) {
        // issue next stage copy first -> lands during this chunk's compute
        if (kc + 1 < KCHUNKS) STAGE_COPY((kc + 1) & 1, kc + 1);

        const uint32_t stg = sb + (uint32_t)(kc & 1) * STAGE_B;
        const uint32_t sA = stg + (uint32_t)(warp_m * 64 * RSTRIDE_B) + laneoff;
        const uint32_t sB = stg + ATILE_B + (uint32_t)(warp_n * 64 * RSTRIDE_B) + laneoff;

        if (active) {
#pragma unroll
            for (int kh = 0; kh < 4; kh++) {
                const uint32_t ka = kh * 32;   // 16 halves = 32 bytes
                uint32_t af[4][4], bf[4][4];
#pragma unroll
                for (int mi = 0; mi < 4; mi++) ldmatrix_x4(af[mi], sA + mi * (16 * RSTRIDE_B) + ka);
#pragma unroll
                for (int np = 0; np < 4; np++) ldmatrix_x4(bf[np], sB + np * (16 * RSTRIDE_B) + ka);
#pragma unroll
                for (int mi = 0; mi < 4; mi++) {
#pragma unroll
                    for (int nj = 0; nj < 8; nj++) {
                        const int np = nj >> 1, h = nj & 1;
                        mma16816_f16(hacc[mi][nj], af[mi], bf[np][h], bf[np][h + 2]);
                    }
                }
            }
        }

        if (kc + 1 < KCHUNKS) {
            asm volatile("cp.async.wait_group 0;" ::: "memory");
            __syncthreads();   // next stage visible; this stage free for overwrite next iter
        }
    }

    // ---------------- epilogue: s = a2[m] - 2*ab, min over m ----------------
    if (active) {
        float a2r[8];
        {
            const float* a2p = g_a2 + m0 + warp_m * 64 + (lane >> 2);
#pragma unroll
            for (int mi = 0; mi < 4; mi++) {
                a2r[2 * mi]     = a2p[mi * 16];
                a2r[2 * mi + 1] = a2p[mi * 16 + 8];
            }
        }
        float v[16];
#pragma unroll
        for (int i = 0; i < 16; i++) v[i] = 3.402823466e38f;
#pragma unroll
        for (int mi = 0; mi < 4; mi++) {
#pragma unroll
            for (int nj = 0; nj < 8; nj++) {
                float2 h0 = __half22float2(*(const __half2*)&hacc[mi][nj][0]);  // row r,   cols n,n+1
                float2 h1 = __half22float2(*(const __half2*)&hacc[mi][nj][1]);  // row r+8, cols n,n+1
                v[nj * 2]     = fminf(v[nj * 2],     fmaf(-2.f, h0.x, a2r[2 * mi]));
                v[nj * 2 + 1] = fminf(v[nj * 2 + 1], fmaf(-2.f, h0.y, a2r[2 * mi]));
                v[nj * 2]     = fminf(v[nj * 2],     fmaf(-2.f, h1.x, a2r[2 * mi + 1]));
                v[nj * 2 + 1] = fminf(v[nj * 2 + 1], fmaf(-2.f, h1.y, a2r[2 * mi + 1]));
            }
        }
#pragma unroll
        for (int o = 4; o <= 16; o <<= 1) {
#pragma unroll
            for (int i = 0; i < 16; i++) v[i] = fminf(v[i], __shfl_xor_sync(0xFFFFFFFFu, v[i], o));
        }
        if (lane < 4) {
#pragma unroll
            for (int nj = 0; nj < 8; nj++) {
                int col = warp_n * 64 + nj * 8 + lane * 2;
                atomicMin(&colmin[col],     fkey(v[nj * 2]));
                atomicMin(&colmin[col + 1], fkey(v[nj * 2 + 1]));
            }
        }
    }
    __syncthreads();
    if (tid < NT) atomicMin(&g_minkey[n0 + tid], colmin[tid]);
#undef STAGE_COPY
}

// ---------------- postprocess: finalize + per-image max (one block per image) ----------------
__global__ void finalize_max_kernel(float* __restrict__ out) {
    int b = blockIdx.x, tid = threadIdx.x;
    float mx = -3.402823466e38f;
    for (int i = tid; i < GH * GH; i += 256) {
        int q = b * GH * GH + i;
        unsigned k = g_minkey[q];
        unsigned bits = (k & 0x80000000u) ? (k ^ 0x80000000u) : ~k;
        float s = __uint_as_float(bits);
        float d = sqrtf(fmaxf(s + g_b2[q], 0.f));
        g_patch[q] = d;
        mx = fmaxf(mx, d);
    }
#pragma unroll
    for (int o = 16; o > 0; o >>= 1) mx = fmaxf(mx, __shfl_xor_sync(0xFFFFFFFFu, mx, o));
    __shared__ float s[8];
    if ((tid & 31) == 0) s[tid >> 5] = mx;
    __syncthreads();
    if (tid == 0) {
        float m = s[0];
#pragma unroll
        for (int i = 1; i < 8; i++) m = fmaxf(m, s[i]);
        out[b] = m;
    }
}

// ---------------- resize (bilinear) + horizontal blur, one block per output row ----------------
__global__ void resize_blur_x_kernel() {
    __shared__ float row[OH];
    __shared__ float w[33];
    int r = blockIdx.x;            // b*224 + y
    int b = r / OH, y = r % OH;
    int x = threadIdx.x;           // 0..223
    if (x < 33) { float t = (float)(x - 16); w[x] = expf(-t * t * (1.0f / 32.0f)); }

    // bilinear sample for (y, x) of image b directly from 28x28 patch grid
    float sy = fminf(fmaxf((y + 0.5f) * 0.125f - 0.5f, 0.f), (float)(GH - 1));
    int y0 = (int)sy; float fy = sy - y0; int y1 = min(y0 + 1, GH - 1);
    float sx = fminf(fmaxf((x + 0.5f) * 0.125f - 0.5f, 0.f), (float)(GH - 1));
    int x0 = (int)sx; float fx = sx - x0; int x1 = min(x0 + 1, GH - 1);
    const float* g = g_patch + b * GH * GH;
    row[x] = (1.f - fy) * ((1.f - fx) * g[y0 * GH + x0] + fx * g[y0 * GH + x1])
           +        fy  * ((1.f - fx) * g[y1 * GH + x0] + fx * g[y1 * GH + x1]);
    __syncthreads();

    float wsum = 0.f;
#pragma unroll
    for (int jj = 0; jj < 33; jj++) wsum += w[jj];
    float acc = 0.f;
#pragma unroll
    for (int t = -16; t <= 16; t++) {
        int ix = x + t;
        ix = (ix < 0) ? -ix : ((ix > OH - 1) ? (2 * OH - 2 - ix) : ix);
        acc += w[t + 16] * row[ix];
    }
    g_tmp[r * OH + x] = acc / wsum;
}

__global__ void blur_y_kernel(float* __restrict__ out) {
    __shared__ float w[33];
    int r = blockIdx.x;            // b*224 + y
    int b = r / OH, y = r % OH;
    int x = threadIdx.x;
    if (x < 33) { float t = (float)(x - 16); w[x] = expf(-t * t * (1.0f / 32.0f)); }
    __syncthreads();
    float wsum = 0.f;
#pragma unroll
    for (int jj = 0; jj < 33; jj++) wsum += w[jj];
    float acc = 0.f;
#pragma unroll
    for (int t = -16; t <= 16; t++) {
        int iy = y + t;
        iy = (iy < 0) ? -iy : ((iy > OH - 1) ? (2 * OH - 2 - iy) : iy);
        acc += w[t + 16] * g_tmp[(b * OH + iy) * OH + x];
    }
    out[r * OH + x] = acc / wsum;
}

// ---------------- launch ----------------
extern "C" void kernel_launch(void* const* d_in, const int* in_sizes, int n_in,
                              void* d_out, int out_size) {
    const float* coreset  = (const float*)d_in[0];
    const float* features = (const float*)d_in[1];
    float* out = (float*)d_out;

    cudaFuncSetAttribute(gemm_min_kernel, cudaFuncAttributeMaxDynamicSharedMemorySize, SMEM_BYTES);

    convert_all_kernel<<<A_BLOCKS + B_BLOCKS, 256>>>(coreset, features);  // A + B + minkey init

    dim3 grid(Q_PAD / NT, M_PAD / MT);   // (13, 391): x inner -> A-tile L2 reuse
    gemm_min_kernel<<<grid, 256, SMEM_BYTES>>>();

    finalize_max_kernel<<<BATCH, 256>>>(out);                    // out[0..3] = image scores
    resize_blur_x_kernel<<<BATCH * OH, OH>>>();
    blur_y_kernel<<<BATCH * OH, OH>>>(out + BATCH);              // out[4..] = masks
}